// round 12
// baseline (speedup 1.0000x reference)
#include <cuda_runtime.h>
#include <cuda_fp16.h>
#include <cstdint>

#define HIDDEN 1024
#define INTER  4096
#define NE     8
#define NTOK   8192
#define NSLOT  (2*NTOK)      // 16384 assignments
#define CAP    17408         // 16384 + 8*128 padding
#define MAXTILES 136

// ---------------- device-global scratch (no allocs allowed) ----------------
__device__ int    g_list_token[CAP];
__device__ int    g_topidx[NSLOT];
__device__ float  g_topw[NSLOT];
__device__ int    g_slot[NSLOT];
__device__ int    g_cnt[NE];
__device__ int    g_cursor[NE];
__device__ int    g_cnt_top1[NE];
__device__ float  g_probsum[NE];
__device__ int    g_poff[NE];
__device__ int    g_ntiles;
__device__ int    g_tile_e[MAXTILES];
__device__ int    g_tile_row0[MAXTILES];
__device__ __half g_xh[(size_t)CAP * HIDDEN];          // gathered x, fp16
__device__ __half g_w1h[(size_t)NE * INTER * HIDDEN];  // W1^T: [e][n][k], fp16
__device__ __half g_w2h[(size_t)NE * HIDDEN * INTER];  // W2^T: [e][n][k], fp16
__device__ __half g_h[(size_t)CAP * INTER];            // silu(x@W1), fp16
__device__ float  g_y[(size_t)CAP * HIDDEN];           // h@W2, fp32

// ---------------- helpers ----------------
__device__ __forceinline__ uint32_t smem_u32(const void* p) {
    uint32_t r;
    asm("{ .reg .u64 t; cvta.to.shared.u64 t, %1; cvt.u32.u64 %0, t; }" : "=r"(r) : "l"(p));
    return r;
}
#define CPA(dst, src) asm volatile("cp.async.cg.shared.global [%0], [%1], 16;" :: "r"(dst), "l"(src))
#define LDSM4(r0, r1, r2, r3, a)                                              \
    asm volatile("ldmatrix.sync.aligned.m8n8.x4.shared.b16 {%0,%1,%2,%3}, [%4];" \
                 : "=r"(r0), "=r"(r1), "=r"(r2), "=r"(r3) : "r"(a))

// ---------------- small kernels ----------------
__global__ void init_kernel() {
    int i = blockIdx.x * blockDim.x + threadIdx.x;
    if (i < CAP) g_list_token[i] = 0;
    if (i < NE) {
        g_cnt[i] = 0; g_cursor[i] = 0; g_cnt_top1[i] = 0; g_probsum[i] = 0.f;
    }
}

__global__ void router_kernel(const float* __restrict__ x,
                              const float* __restrict__ rw) {
    int t = blockIdx.x * 8 + (threadIdx.x >> 5);
    int lane = threadIdx.x & 31;
    const float* xr = x + (size_t)t * HIDDEN;
    float acc[NE];
#pragma unroll
    for (int e = 0; e < NE; e++) acc[e] = 0.f;
    for (int i = lane; i < HIDDEN; i += 32) {
        float xv = xr[i];
#pragma unroll
        for (int e = 0; e < NE; e++) acc[e] += xv * rw[e * HIDDEN + i];
    }
#pragma unroll
    for (int e = 0; e < NE; e++) {
#pragma unroll
        for (int o = 16; o > 0; o >>= 1)
            acc[e] += __shfl_xor_sync(0xffffffffu, acc[e], o);
    }
    if (lane == 0) {
        float mx = acc[0];
#pragma unroll
        for (int e = 1; e < NE; e++) mx = fmaxf(mx, acc[e]);
        float p[NE], s = 0.f;
#pragma unroll
        for (int e = 0; e < NE; e++) { p[e] = expf(acc[e] - mx); s += p[e]; }
        float inv = 1.f / s;
#pragma unroll
        for (int e = 0; e < NE; e++) p[e] *= inv;
        int i0 = 0;
#pragma unroll
        for (int e = 1; e < NE; e++) if (p[e] > p[i0]) i0 = e;
        int i1 = (i0 == 0) ? 1 : 0;
#pragma unroll
        for (int e = 0; e < NE; e++) if (e != i0 && p[e] > p[i1]) i1 = e;
        float w0 = p[i0], w1 = p[i1];
        float wn = 1.f / (w0 + w1);
        g_topidx[2 * t] = i0; g_topidx[2 * t + 1] = i1;
        g_topw[2 * t] = w0 * wn; g_topw[2 * t + 1] = w1 * wn;
        atomicAdd(&g_cnt[i0], 1); atomicAdd(&g_cnt[i1], 1);
        atomicAdd(&g_cnt_top1[i0], 1);
#pragma unroll
        for (int e = 0; e < NE; e++) atomicAdd(&g_probsum[e], p[e]);
    }
}

__global__ void offsets_kernel() {
    int off = 0, tiles = 0;
    for (int e = 0; e < NE; e++) {
        g_poff[e] = off;
        int nt = (g_cnt[e] + 127) >> 7;
        for (int j = 0; j < nt; j++) {
            g_tile_e[tiles] = e;
            g_tile_row0[tiles] = off + j * 128;
            tiles++;
        }
        off += nt * 128;
    }
    g_ntiles = tiles;
}

__global__ void scatter_kernel() {
    int id = blockIdx.x * blockDim.x + threadIdx.x;
    if (id >= NSLOT) return;
    int t = id >> 1;
    int e = g_topidx[id];
    int pos = g_poff[e] + atomicAdd(&g_cursor[e], 1);
    g_list_token[pos] = t;
    g_slot[id] = pos;
}

// gather x rows into dense slot order, fp32 -> fp16
__global__ void gather_kernel(const float* __restrict__ x) {
    int row = blockIdx.x;
    int tok = g_list_token[row];
    const float4* s = (const float4*)(x + (size_t)tok * HIDDEN);
    __half2* d = (__half2*)(g_xh + (size_t)row * HIDDEN);
    int i = threadIdx.x;  // 256 threads * 4 floats = 1024
    float4 v = s[i];
    d[2 * i]     = __floats2half2_rn(v.x, v.y);
    d[2 * i + 1] = __floats2half2_rn(v.z, v.w);
}

// W [e][KD][ND] fp32 -> Wh [e][ND][KD] fp16. Block tile k64 x n32.
// Reads: 32 floats/row = 128B sectors. Writes: 32 half2 = 128B sectors.
// blockDim (32,8), grid (KD/64, ND/32, NE).
template <int KD, int ND>
__global__ void transconv_kernel(const float* __restrict__ W, __half* __restrict__ Wh) {
    __shared__ float tile[32][65];   // [n][k] padded
    int e = blockIdx.z;
    int k0 = blockIdx.x * 64, n0 = blockIdx.y * 32;
    const float* Wb = W + (size_t)e * KD * ND;
    __half* Whb = Wh + (size_t)e * KD * ND;
    int tx = threadIdx.x, ty = threadIdx.y;
#pragma unroll
    for (int i = ty; i < 64; i += 8)
        tile[tx][i] = Wb[(size_t)(k0 + i) * ND + n0 + tx];
    __syncthreads();
#pragma unroll
    for (int j = ty; j < 32; j += 8) {
        __half2 h = __floats2half2_rn(tile[j][2 * tx], tile[j][2 * tx + 1]);
        *(__half2*)&Whb[(size_t)(n0 + j) * KD + k0 + 2 * tx] = h;
    }
}

// ---------------- fp16 mma.sync GEMM ----------------
// Block tile 128(M) x 128(N), kc = 64. 8 warps as 4(M) x 2(N), warp tile 32x64.
// A smem: [128][64] fp16 (128B rows, XOR-swizzled). B smem: [128 n][64 k] fp16.
// 3 stages x 32KB = 96KB; __launch_bounds__(256,2) -> 2 CTAs/SM.
// MODE 0: g_h = silu(g_xh @ g_w1h^T)  K=1024, N=4096, out fp16
// MODE 1: g_y = g_h @ g_w2h^T         K=4096, N=1024, out fp32
template <int MODE>
__global__ __launch_bounds__(256, 2) void moe_gemm() {
    constexpr int K  = (MODE == 0) ? HIDDEN : INTER;
    constexpr int N  = (MODE == 0) ? INTER : HIDDEN;
    constexpr int KC = 64;
    constexpr int KT = K / KC;
    constexpr int NSTG = 3;
    constexpr int ABYTES = 128 * KC * 2;    // 16 KB
    constexpr int STG_B = 2 * ABYTES;       // 32 KB (A + B)

    extern __shared__ char smraw[];

    const int mt = blockIdx.y;
    if (mt >= g_ntiles) return;
    const int row0 = g_tile_row0[mt];
    const int e = g_tile_e[mt];
    const int n0 = blockIdx.x * 128;
    const __half* A = ((MODE == 0) ? (const __half*)g_xh : (const __half*)g_h)
                      + (size_t)row0 * K;
    const __half* B = ((MODE == 0) ? (const __half*)g_w1h : (const __half*)g_w2h)
                      + ((size_t)e * N + n0) * K;

    const int tid = threadIdx.x;
    const int lane = tid & 31, w = tid >> 5;
    const int wm = w & 3, wn = w >> 2;         // 4 x 2 warp grid
    const int g = lane >> 2, tq = lane & 3;

    uint32_t smb = smem_u32(smraw);

    // cp.async bases: row r0 = tid>>3, col c0 = tid&7; rows advance by 32
    // (r&7 invariant under +32 -> swizzled smem offset advances by exactly 4096B).
    const int r0 = tid >> 3, c0 = tid & 7;
    const uint32_t sw0 = (uint32_t)r0 * 128 + (((uint32_t)c0 * 16) ^ (((uint32_t)(r0 & 7)) << 4));
    const uint32_t aDst0 = smb + sw0;
    const uint32_t bDst0 = smb + ABYTES + sw0;
    const __half* aSrc0 = A + (size_t)r0 * K + c0 * 8;
    const __half* bSrc0 = B + (size_t)r0 * K + c0 * 8;

#define LOADC(j, s)                                                            \
    do {                                                                       \
        uint32_t so_ = (uint32_t)(s) * STG_B;                                  \
        int ko_ = (j) * KC;                                                    \
        _Pragma("unroll")                                                      \
        for (int i = 0; i < 4; i++)                                            \
            CPA(aDst0 + i * 4096 + so_, aSrc0 + (size_t)i * 32 * K + ko_);     \
        _Pragma("unroll")                                                      \
        for (int i = 0; i < 4; i++)                                            \
            CPA(bDst0 + i * 4096 + so_, bSrc0 + (size_t)i * 32 * K + ko_);     \
    } while (0)

    // ldmatrix base addresses; XOR column constant per thread
    const uint32_t xorc = ((uint32_t)(lane & 7)) << 4;
    // A quadrants: t0-7: m0-7/k0 | t8-15: m8-15/k0 | t16-23: m0-7/k8 | t24-31: m8-15/k8
    uint32_t aRow = (uint32_t)(wm * 32 + (lane & 7) + ((lane >> 3) & 1) * 8);
    uint32_t aCol0 = ((uint32_t)(lane >> 4)) << 4;       // 0 or 16 bytes (k8 half)
    uint32_t aBase[2];
#pragma unroll
    for (int mi = 0; mi < 2; mi++) aBase[mi] = smb + (aRow + mi * 16) * 128;
    // B quadrants: t0-7: n0-7/k0 | t8-15: n0-7/k8 | t16-23: n8-15/k0 | t24-31: n8-15/k8
    uint32_t bCol0 = ((uint32_t)((lane >> 3) & 1)) << 4;
    uint32_t bBase[4];
#pragma unroll
    for (int p = 0; p < 4; p++) {
        uint32_t bRow = (uint32_t)(wn * 64 + p * 16 + (lane & 7) + ((lane >> 4) << 3));
        bBase[p] = smb + ABYTES + bRow * 128;
    }

    float acc[2][8][4];
#pragma unroll
    for (int mi = 0; mi < 2; mi++)
#pragma unroll
        for (int ni = 0; ni < 8; ni++)
#pragma unroll
            for (int q = 0; q < 4; q++) acc[mi][ni][q] = 0.f;

    // prologue: NSTG stages in flight
#pragma unroll
    for (int j = 0; j < NSTG; j++) {
        LOADC(j, j);
        asm volatile("cp.async.commit_group;");
    }

    int sbuf = 0;
    for (int j = 0; j < KT; j++) {
        asm volatile("cp.async.wait_group %0;" :: "n"(NSTG - 1));
        __syncthreads();
        const uint32_t so = (uint32_t)sbuf * STG_B;

#pragma unroll
        for (int kf = 0; kf < 4; kf++) {
            const uint32_t kb = (uint32_t)kf * 32;
            uint32_t afr[2][4];
#pragma unroll
            for (int mi = 0; mi < 2; mi++) {
                uint32_t ad = aBase[mi] + so + ((aCol0 | kb) ^ xorc);
                LDSM4(afr[mi][0], afr[mi][1], afr[mi][2], afr[mi][3], ad);
            }
            uint32_t bfr[8][2];
#pragma unroll
            for (int p = 0; p < 4; p++) {
                uint32_t bd = bBase[p] + so + ((bCol0 | kb) ^ xorc);
                LDSM4(bfr[2 * p][0], bfr[2 * p][1], bfr[2 * p + 1][0], bfr[2 * p + 1][1], bd);
            }
#pragma unroll
            for (int mi = 0; mi < 2; mi++)
#pragma unroll
                for (int ni = 0; ni < 8; ni++) {
                    asm volatile(
                        "mma.sync.aligned.m16n8k16.row.col.f32.f16.f16.f32 "
                        "{%0,%1,%2,%3},{%4,%5,%6,%7},{%8,%9},{%0,%1,%2,%3};"
                        : "+f"(acc[mi][ni][0]), "+f"(acc[mi][ni][1]),
                          "+f"(acc[mi][ni][2]), "+f"(acc[mi][ni][3])
                        : "r"(afr[mi][0]), "r"(afr[mi][1]),
                          "r"(afr[mi][2]), "r"(afr[mi][3]),
                          "r"(bfr[ni][0]), "r"(bfr[ni][1]));
                }
        }

        __syncthreads();
        if (j + NSTG < KT) LOADC(j + NSTG, sbuf);
        asm volatile("cp.async.commit_group;");
        sbuf = (sbuf == NSTG - 1) ? 0 : sbuf + 1;
    }
#undef LOADC

    // epilogue
#pragma unroll
    for (int mi = 0; mi < 2; mi++) {
        int r = row0 + wm * 32 + mi * 16 + g;
#pragma unroll
        for (int ni = 0; ni < 8; ni++) {
            int c = n0 + wn * 64 + ni * 8 + 2 * tq;
            float v0 = acc[mi][ni][0], v1 = acc[mi][ni][1];
            float v2 = acc[mi][ni][2], v3 = acc[mi][ni][3];
            if (MODE == 0) {  // silu, write fp16
                v0 = v0 / (1.f + __expf(-v0));
                v1 = v1 / (1.f + __expf(-v1));
                v2 = v2 / (1.f + __expf(-v2));
                v3 = v3 / (1.f + __expf(-v3));
                __half* H = (__half*)g_h;
                *(__half2*)&H[(size_t)r * N + c] = __floats2half2_rn(v0, v1);
                *(__half2*)&H[(size_t)(r + 8) * N + c] = __floats2half2_rn(v2, v3);
            } else {
                float* Y = (float*)g_y;
                *(float2*)&Y[(size_t)r * N + c] = make_float2(v0, v1);
                *(float2*)&Y[(size_t)(r + 8) * N + c] = make_float2(v2, v3);
            }
        }
    }
}

// ---------------- combine (+fused aux) ----------------
__global__ void combine_kernel(float* __restrict__ out, int out_size) {
    size_t idx = (size_t)blockIdx.x * blockDim.x + threadIdx.x;
    int t = (int)(idx >> 10);
    int c = (int)(idx & 1023);
    float v = g_topw[2 * t]     * g_y[(size_t)g_slot[2 * t]     * HIDDEN + c]
            + g_topw[2 * t + 1] * g_y[(size_t)g_slot[2 * t + 1] * HIDDEN + c];
    out[idx] = v;
    if (blockIdx.x == 0 && threadIdx.x == 0 && out_size > NTOK * HIDDEN) {
        float a = 0.f;
        for (int e = 0; e < NE; e++)
            a += ((float)g_cnt_top1[e] / (float)NTOK) * (g_probsum[e] / (float)NTOK);
        out[(size_t)NTOK * HIDDEN] = a * (float)NE;
    }
}

// ---------------- launch ----------------
extern "C" void kernel_launch(void* const* d_in, const int* in_sizes, int n_in,
                              void* d_out, int out_size) {
    const float* x  = (const float*)d_in[0];
    const float* rw = (const float*)d_in[1];
    const float* w1 = (const float*)d_in[2];
    const float* w2 = (const float*)d_in[3];
    float* out = (float*)d_out;

    const int SMEMB = 3 * 32 * 1024;  // 3 stages x 32KB = 96KB

    cudaFuncSetAttribute(moe_gemm<0>, cudaFuncAttributeMaxDynamicSharedMemorySize, SMEMB);
    cudaFuncSetAttribute(moe_gemm<1>, cudaFuncAttributeMaxDynamicSharedMemorySize, SMEMB);

    init_kernel<<<(CAP + 255) / 256, 256>>>();
    router_kernel<<<NTOK / 8, 256>>>(x, rw);
    offsets_kernel<<<1, 1>>>();
    scatter_kernel<<<NSLOT / 256, 256>>>();
    gather_kernel<<<CAP, 256>>>(x);

    {   // W1 [e][1024][4096] -> g_w1h [e][4096][1024] fp16; W2 likewise
        __half* w1h; cudaGetSymbolAddress((void**)&w1h, g_w1h);
        __half* w2h; cudaGetSymbolAddress((void**)&w2h, g_w2h);
        transconv_kernel<HIDDEN, INTER><<<dim3(HIDDEN / 64, INTER / 32, NE), dim3(32, 8)>>>(w1, w1h);
        transconv_kernel<INTER, HIDDEN><<<dim3(INTER / 64, HIDDEN / 32, NE), dim3(32, 8)>>>(w2, w2h);
    }

    moe_gemm<0><<<dim3(INTER / 128, MAXTILES), 256, SMEMB>>>();
    moe_gemm<1><<<dim3(HIDDEN / 128, MAXTILES), 256, SMEMB>>>();

    combine_kernel<<<(NTOK * HIDDEN) / 256, 256>>>(out, out_size);
}

// round 15
// speedup vs baseline: 1.0629x; 1.0629x over previous
#include <cuda_runtime.h>
#include <cuda_fp16.h>
#include <cstdint>

#define HIDDEN 1024
#define INTER  4096
#define NE     8
#define NTOK   8192
#define NSLOT  (2*NTOK)      // 16384 assignments
#define CAP    17408         // 16384 + 8*128 padding
#define MAXTILES 136

// ---------------- device-global scratch (no allocs allowed) ----------------
__device__ int    g_list_token[CAP];
__device__ int    g_topidx[NSLOT];
__device__ float  g_topw[NSLOT];
__device__ int    g_slot[NSLOT];
__device__ int    g_cnt[NE];
__device__ int    g_cursor[NE];
__device__ int    g_cnt_top1[NE];
__device__ float  g_probsum[NE];
__device__ int    g_poff[NE];
__device__ int    g_ntiles;
__device__ int    g_tile_e[MAXTILES];
__device__ int    g_tile_row0[MAXTILES];
__device__ __half g_xh[(size_t)CAP * HIDDEN];          // gathered x, fp16
__device__ __half g_w1h[(size_t)NE * INTER * HIDDEN];  // W1^T: [e][n][k], fp16
__device__ __half g_w2h[(size_t)NE * HIDDEN * INTER];  // W2^T: [e][n][k], fp16
__device__ __half g_h[(size_t)CAP * INTER];            // silu(x@W1), fp16
__device__ float  g_y[(size_t)CAP * HIDDEN];           // h@W2, fp32

// ---------------- helpers ----------------
__device__ __forceinline__ uint32_t smem_u32(const void* p) {
    uint32_t r;
    asm("{ .reg .u64 t; cvta.to.shared.u64 t, %1; cvt.u32.u64 %0, t; }" : "=r"(r) : "l"(p));
    return r;
}
#define CPA(dst, src) asm volatile("cp.async.cg.shared.global [%0], [%1], 16;" :: "r"(dst), "l"(src))
#define LDSM4(r0, r1, r2, r3, a)                                              \
    asm volatile("ldmatrix.sync.aligned.m8n8.x4.shared.b16 {%0,%1,%2,%3}, [%4];" \
                 : "=r"(r0), "=r"(r1), "=r"(r2), "=r"(r3) : "r"(a))

// ---------------- small kernels ----------------
__global__ void init_kernel() {
    int i = blockIdx.x * blockDim.x + threadIdx.x;
    if (i < CAP) g_list_token[i] = 0;
    if (i < NE) {
        g_cnt[i] = 0; g_cursor[i] = 0; g_cnt_top1[i] = 0; g_probsum[i] = 0.f;
    }
}

// router body: one warp per token (8 tokens per 256-thread block)
__device__ __forceinline__ void router_body(const float* __restrict__ x,
                                            const float* __restrict__ rw,
                                            int blk, int tid) {
    int t = blk * 8 + (tid >> 5);
    int lane = tid & 31;
    const float* xr = x + (size_t)t * HIDDEN;
    float acc[NE];
#pragma unroll
    for (int e = 0; e < NE; e++) acc[e] = 0.f;
    for (int i = lane; i < HIDDEN; i += 32) {
        float xv = xr[i];
#pragma unroll
        for (int e = 0; e < NE; e++) acc[e] += xv * rw[e * HIDDEN + i];
    }
#pragma unroll
    for (int e = 0; e < NE; e++) {
#pragma unroll
        for (int o = 16; o > 0; o >>= 1)
            acc[e] += __shfl_xor_sync(0xffffffffu, acc[e], o);
    }
    if (lane == 0) {
        float mx = acc[0];
#pragma unroll
        for (int e = 1; e < NE; e++) mx = fmaxf(mx, acc[e]);
        float p[NE], s = 0.f;
#pragma unroll
        for (int e = 0; e < NE; e++) { p[e] = expf(acc[e] - mx); s += p[e]; }
        float inv = 1.f / s;
#pragma unroll
        for (int e = 0; e < NE; e++) p[e] *= inv;
        int i0 = 0;
#pragma unroll
        for (int e = 1; e < NE; e++) if (p[e] > p[i0]) i0 = e;
        int i1 = (i0 == 0) ? 1 : 0;
#pragma unroll
        for (int e = 0; e < NE; e++) if (e != i0 && p[e] > p[i1]) i1 = e;
        float w0 = p[i0], w1 = p[i1];
        float wn = 1.f / (w0 + w1);
        g_topidx[2 * t] = i0; g_topidx[2 * t + 1] = i1;
        g_topw[2 * t] = w0 * wn; g_topw[2 * t + 1] = w1 * wn;
        atomicAdd(&g_cnt[i0], 1); atomicAdd(&g_cnt[i1], 1);
        atomicAdd(&g_cnt_top1[i0], 1);
#pragma unroll
        for (int e = 0; e < NE; e++) atomicAdd(&g_probsum[e], p[e]);
    }
}

// transconv body (R11 version): W [e][KD][ND] fp32 -> Wh [e][ND][KD] fp16
__device__ __forceinline__ void transconv_body(const float* __restrict__ W,
                                               __half* __restrict__ Wh,
                                               int KD, int ND, int idx,
                                               int tx, int ty, float (*tile)[33]) {
    int kx = idx % (KD / 32); int rest = idx / (KD / 32);
    int ny = rest % (ND / 32); int e = rest / (ND / 32);
    int k0 = kx * 32, n0 = ny * 32;
    const float* Wb = W + (size_t)e * KD * ND;
    __half* Whb = Wh + (size_t)e * KD * ND;
#pragma unroll
    for (int i = ty; i < 32; i += 8)
        tile[i][tx] = Wb[(size_t)(k0 + i) * ND + n0 + tx];
    __syncthreads();
#pragma unroll
    for (int i = ty; i < 32; i += 8)
        Whb[(size_t)(n0 + i) * KD + k0 + tx] = __float2half_rn(tile[tx][i]);
}

// fused prep: router (blocks [0,1024)) + W1 transconv ([1024,1024+32768))
//           + W2 transconv (rest). All mutually independent.
#define RT_BLKS   (NTOK / 8)                           // 1024
#define TC1_BLKS  ((HIDDEN / 32) * (INTER / 32) * NE)  // 32768
#define TC2_BLKS  ((INTER / 32) * (HIDDEN / 32) * NE)  // 32768
__global__ void prep_kernel(const float* __restrict__ x,
                            const float* __restrict__ rw,
                            const float* __restrict__ w1,
                            const float* __restrict__ w2) {
    __shared__ float tile[32][33];
    int b = blockIdx.x;
    int tid = threadIdx.x;
    int tx = tid & 31, ty = tid >> 5;
    if (b < RT_BLKS) {
        router_body(x, rw, b, tid);
    } else if (b < RT_BLKS + TC1_BLKS) {
        transconv_body(w1, (__half*)g_w1h, HIDDEN, INTER, b - RT_BLKS, tx, ty, tile);
    } else {
        transconv_body(w2, (__half*)g_w2h, INTER, HIDDEN, b - RT_BLKS - TC1_BLKS, tx, ty, tile);
    }
}

__global__ void offsets_kernel() {
    int off = 0, tiles = 0;
    for (int e = 0; e < NE; e++) {
        g_poff[e] = off;
        int nt = (g_cnt[e] + 127) >> 7;
        for (int j = 0; j < nt; j++) {
            g_tile_e[tiles] = e;
            g_tile_row0[tiles] = off + j * 128;
            tiles++;
        }
        off += nt * 128;
    }
    g_ntiles = tiles;
}

__global__ void scatter_kernel() {
    int id = blockIdx.x * blockDim.x + threadIdx.x;
    if (id >= NSLOT) return;
    int t = id >> 1;
    int e = g_topidx[id];
    int pos = g_poff[e] + atomicAdd(&g_cursor[e], 1);
    g_list_token[pos] = t;
    g_slot[id] = pos;
}

// gather x rows into dense slot order, fp32 -> fp16
__global__ void gather_kernel(const float* __restrict__ x) {
    int row = blockIdx.x;
    int tok = g_list_token[row];
    const float4* s = (const float4*)(x + (size_t)tok * HIDDEN);
    __half2* d = (__half2*)(g_xh + (size_t)row * HIDDEN);
    int i = threadIdx.x;  // 256 threads * 4 floats = 1024
    float4 v = s[i];
    d[2 * i]     = __floats2half2_rn(v.x, v.y);
    d[2 * i + 1] = __floats2half2_rn(v.z, v.w);
}

// ---------------- fp16 mma.sync GEMM (R11 config: best measured) ----------------
// Block tile 128(M) x 128(N), kc = 64. 8 warps as 4(M) x 2(N), warp tile 32x64.
// 3 stages x 32KB = 96KB; __launch_bounds__(256,2) -> 2 CTAs/SM.
// Fragment double-buffering: LDSM for kf+1 issued before MMAs of kf.
// MODE 0: g_h = silu(g_xh @ g_w1h^T)  K=1024, N=4096, out fp16
// MODE 1: g_y = g_h @ g_w2h^T         K=4096, N=1024, out fp32
template <int MODE>
__global__ __launch_bounds__(256, 2) void moe_gemm() {
    constexpr int K  = (MODE == 0) ? HIDDEN : INTER;
    constexpr int N  = (MODE == 0) ? INTER : HIDDEN;
    constexpr int KC = 64;
    constexpr int KT = K / KC;
    constexpr int NSTG = 3;
    constexpr int ABYTES = 128 * KC * 2;    // 16 KB
    constexpr int STG_B = 2 * ABYTES;       // 32 KB (A + B)

    extern __shared__ char smraw[];

    const int mt = blockIdx.y;
    if (mt >= g_ntiles) return;
    const int row0 = g_tile_row0[mt];
    const int e = g_tile_e[mt];
    const int n0 = blockIdx.x * 128;
    const __half* A = ((MODE == 0) ? (const __half*)g_xh : (const __half*)g_h)
                      + (size_t)row0 * K;
    const __half* B = ((MODE == 0) ? (const __half*)g_w1h : (const __half*)g_w2h)
                      + ((size_t)e * N + n0) * K;

    const int tid = threadIdx.x;
    const int lane = tid & 31, w = tid >> 5;
    const int wm = w & 3, wn = w >> 2;         // 4 x 2 warp grid
    const int g = lane >> 2, tq = lane & 3;

    uint32_t smb = smem_u32(smraw);

    const int r0 = tid >> 3, c0 = tid & 7;
    const uint32_t sw0 = (uint32_t)r0 * 128 + (((uint32_t)c0 * 16) ^ (((uint32_t)(r0 & 7)) << 4));
    const uint32_t aDst0 = smb + sw0;
    const uint32_t bDst0 = smb + ABYTES + sw0;
    const __half* aSrc0 = A + (size_t)r0 * K + c0 * 8;
    const __half* bSrc0 = B + (size_t)r0 * K + c0 * 8;

#define LOADC(j, s)                                                            \
    do {                                                                       \
        uint32_t so_ = (uint32_t)(s) * STG_B;                                  \
        int ko_ = (j) * KC;                                                    \
        _Pragma("unroll")                                                      \
        for (int i = 0; i < 4; i++)                                            \
            CPA(aDst0 + i * 4096 + so_, aSrc0 + (size_t)i * 32 * K + ko_);     \
        _Pragma("unroll")                                                      \
        for (int i = 0; i < 4; i++)                                            \
            CPA(bDst0 + i * 4096 + so_, bSrc0 + (size_t)i * 32 * K + ko_);     \
    } while (0)

    const uint32_t xorc = ((uint32_t)(lane & 7)) << 4;
    uint32_t aRow = (uint32_t)(wm * 32 + (lane & 7) + ((lane >> 3) & 1) * 8);
    uint32_t aCol0 = ((uint32_t)(lane >> 4)) << 4;
    uint32_t aBase[2];
#pragma unroll
    for (int mi = 0; mi < 2; mi++) aBase[mi] = smb + (aRow + mi * 16) * 128;
    uint32_t bCol0 = ((uint32_t)((lane >> 3) & 1)) << 4;
    uint32_t bBase[4];
#pragma unroll
    for (int p = 0; p < 4; p++) {
        uint32_t bRow = (uint32_t)(wn * 64 + p * 16 + (lane & 7) + ((lane >> 4) << 3));
        bBase[p] = smb + ABYTES + bRow * 128;
    }

    // double-buffered fragments
    uint32_t afr[2][2][4];
    uint32_t bfr[2][8][2];

#define LOADF(kf, b, so_)                                                      \
    do {                                                                       \
        const uint32_t kb_ = (uint32_t)(kf) * 32;                              \
        _Pragma("unroll")                                                      \
        for (int mi = 0; mi < 2; mi++) {                                       \
            uint32_t ad = aBase[mi] + (so_) + ((aCol0 | kb_) ^ xorc);          \
            LDSM4(afr[b][mi][0], afr[b][mi][1], afr[b][mi][2], afr[b][mi][3], ad); \
        }                                                                      \
        _Pragma("unroll")                                                      \
        for (int p = 0; p < 4; p++) {                                          \
            uint32_t bd = bBase[p] + (so_) + ((bCol0 | kb_) ^ xorc);           \
            LDSM4(bfr[b][2 * p][0], bfr[b][2 * p][1],                          \
                  bfr[b][2 * p + 1][0], bfr[b][2 * p + 1][1], bd);             \
        }                                                                      \
    } while (0)

    float acc[2][8][4];
#pragma unroll
    for (int mi = 0; mi < 2; mi++)
#pragma unroll
        for (int ni = 0; ni < 8; ni++)
#pragma unroll
            for (int q = 0; q < 4; q++) acc[mi][ni][q] = 0.f;

#pragma unroll
    for (int j = 0; j < NSTG; j++) {
        LOADC(j, j);
        asm volatile("cp.async.commit_group;");
    }

    int sbuf = 0;
    for (int j = 0; j < KT; j++) {
        asm volatile("cp.async.wait_group %0;" :: "n"(NSTG - 1));
        __syncthreads();
        const uint32_t so = (uint32_t)sbuf * STG_B;

        LOADF(0, 0, so);
#pragma unroll
        for (int kf = 0; kf < 4; kf++) {
            const int cur = kf & 1;
            if (kf < 3) LOADF(kf + 1, cur ^ 1, so);
#pragma unroll
            for (int mi = 0; mi < 2; mi++)
#pragma unroll
                for (int ni = 0; ni < 8; ni++) {
                    asm volatile(
                        "mma.sync.aligned.m16n8k16.row.col.f32.f16.f16.f32 "
                        "{%0,%1,%2,%3},{%4,%5,%6,%7},{%8,%9},{%0,%1,%2,%3};"
                        : "+f"(acc[mi][ni][0]), "+f"(acc[mi][ni][1]),
                          "+f"(acc[mi][ni][2]), "+f"(acc[mi][ni][3])
                        : "r"(afr[cur][mi][0]), "r"(afr[cur][mi][1]),
                          "r"(afr[cur][mi][2]), "r"(afr[cur][mi][3]),
                          "r"(bfr[cur][ni][0]), "r"(bfr[cur][ni][1]));
                }
        }

        __syncthreads();
        if (j + NSTG < KT) LOADC(j + NSTG, sbuf);
        asm volatile("cp.async.commit_group;");
        sbuf = (sbuf == NSTG - 1) ? 0 : sbuf + 1;
    }
#undef LOADC
#undef LOADF

    // epilogue
#pragma unroll
    for (int mi = 0; mi < 2; mi++) {
        int r = row0 + wm * 32 + mi * 16 + g;
#pragma unroll
        for (int ni = 0; ni < 8; ni++) {
            int c = n0 + wn * 64 + ni * 8 + 2 * tq;
            float v0 = acc[mi][ni][0], v1 = acc[mi][ni][1];
            float v2 = acc[mi][ni][2], v3 = acc[mi][ni][3];
            if (MODE == 0) {  // silu, write fp16
                v0 = v0 / (1.f + __expf(-v0));
                v1 = v1 / (1.f + __expf(-v1));
                v2 = v2 / (1.f + __expf(-v2));
                v3 = v3 / (1.f + __expf(-v3));
                __half* H = (__half*)g_h;
                *(__half2*)&H[(size_t)r * N + c] = __floats2half2_rn(v0, v1);
                *(__half2*)&H[(size_t)(r + 8) * N + c] = __floats2half2_rn(v2, v3);
            } else {
                float* Y = (float*)g_y;
                *(float2*)&Y[(size_t)r * N + c] = make_float2(v0, v1);
                *(float2*)&Y[(size_t)(r + 8) * N + c] = make_float2(v2, v3);
            }
        }
    }
}

// ---------------- combine (+fused aux) ----------------
__global__ void combine_kernel(float* __restrict__ out, int out_size) {
    size_t idx = (size_t)blockIdx.x * blockDim.x + threadIdx.x;
    int t = (int)(idx >> 10);
    int c = (int)(idx & 1023);
    float v = g_topw[2 * t]     * g_y[(size_t)g_slot[2 * t]     * HIDDEN + c]
            + g_topw[2 * t + 1] * g_y[(size_t)g_slot[2 * t + 1] * HIDDEN + c];
    out[idx] = v;
    if (blockIdx.x == 0 && threadIdx.x == 0 && out_size > NTOK * HIDDEN) {
        float a = 0.f;
        for (int e = 0; e < NE; e++)
            a += ((float)g_cnt_top1[e] / (float)NTOK) * (g_probsum[e] / (float)NTOK);
        out[(size_t)NTOK * HIDDEN] = a * (float)NE;
    }
}

// ---------------- launch ----------------
extern "C" void kernel_launch(void* const* d_in, const int* in_sizes, int n_in,
                              void* d_out, int out_size) {
    const float* x  = (const float*)d_in[0];
    const float* rw = (const float*)d_in[1];
    const float* w1 = (const float*)d_in[2];
    const float* w2 = (const float*)d_in[3];
    float* out = (float*)d_out;

    const int SMEMB = 3 * 32 * 1024;  // 3 stages x 32KB = 96KB

    cudaFuncSetAttribute(moe_gemm<0>, cudaFuncAttributeMaxDynamicSharedMemorySize, SMEMB);
    cudaFuncSetAttribute(moe_gemm<1>, cudaFuncAttributeMaxDynamicSharedMemorySize, SMEMB);

    init_kernel<<<(CAP + 255) / 256, 256>>>();
    prep_kernel<<<RT_BLKS + TC1_BLKS + TC2_BLKS, 256>>>(x, rw, w1, w2);
    offsets_kernel<<<1, 1>>>();
    scatter_kernel<<<NSLOT / 256, 256>>>();
    gather_kernel<<<CAP, 256>>>(x);

    moe_gemm<0><<<dim3(INTER / 128, MAXTILES), 256, SMEMB>>>();
    moe_gemm<1><<<dim3(HIDDEN / 128, MAXTILES), 256, SMEMB>>>();

    combine_kernel<<<(NTOK * HIDDEN) / 256, 256>>>(out, out_size);
}